// round 16
// baseline (speedup 1.0000x reference)
#include <cuda_runtime.h>
#include <cuda_fp16.h>
#include <cstdint>
#include <cstring>
#include <math.h>

// ---------------------------------------------------------------------------
// SelfAttnV3  B=8, N=2048, D=1024
// HMMA fp16 2-term split GEMMs (A truncated to fp16, B split hi/lo fp16).
// R15: CTA tile 256x128, warp tile 64x64 (4m x 2n warps) -- 1.67x fewer
//      LDSM bytes per mma; single barrier per mainloop iteration.
// ---------------------------------------------------------------------------
#define BB 8
#define NN 2048
#define DD 1024

// ------------------------- device scratch (no allocs) ----------------------
__device__ float g_qkv[(long long)BB * NN * 3 * DD];      // 192 MB
__device__ float g_scores[(long long)BB * NN * NN];       // 128 MB

__device__ __half g_xh[(long long)BB * NN * DD];          // A sides (single)
__device__ __half g_qh[(long long)BB * NN * DD];
__device__ __half g_ph[(long long)BB * NN * NN];
__device__ __half g_ath[(long long)BB * NN * DD];

__device__ __half g_wqt_h[(long long)3 * DD * DD];        // B sides (split)
__device__ __half g_wqt_l[(long long)3 * DD * DD];
__device__ __half g_wot_h[(long long)DD * DD];
__device__ __half g_wot_l[(long long)DD * DD];
__device__ __half g_kh[(long long)BB * NN * DD];
__device__ __half g_kl[(long long)BB * NN * DD];
__device__ __half g_vth[(long long)BB * DD * NN];
__device__ __half g_vtl[(long long)BB * DD * NN];

// ------------------------------ PTX helpers --------------------------------
__device__ __forceinline__ uint32_t smem_u32(const void* p) {
    uint32_t a;
    asm("{ .reg .u64 t; cvta.to.shared.u64 t, %1; cvt.u32.u64 %0, t; }"
        : "=r"(a) : "l"(p));
    return a;
}

#define CP_ASYNC16(dst, src) \
    asm volatile("cp.async.cg.shared.global [%0], [%1], 16;" :: "r"(dst), "l"(src) : "memory")
#define CP_ASYNC_COMMIT() asm volatile("cp.async.commit_group;" ::: "memory")
#define CP_ASYNC_WAIT(n)  asm volatile("cp.async.wait_group %0;" :: "n"(n) : "memory")

__device__ __forceinline__ void ldsm4(uint32_t r[4], uint32_t addr) {
    asm volatile("ldmatrix.sync.aligned.m8n8.x4.shared.b16 {%0,%1,%2,%3}, [%4];"
                 : "=r"(r[0]), "=r"(r[1]), "=r"(r[2]), "=r"(r[3]) : "r"(addr));
}

__device__ __forceinline__ void mma_f16(float c[4], const uint32_t a[4],
                                        uint32_t b0, uint32_t b1) {
    asm volatile(
        "mma.sync.aligned.m16n8k16.row.col.f32.f16.f16.f32 "
        "{%0,%1,%2,%3}, {%4,%5,%6,%7}, {%8,%9}, {%0,%1,%2,%3};"
        : "+f"(c[0]), "+f"(c[1]), "+f"(c[2]), "+f"(c[3])
        : "r"(a[0]), "r"(a[1]), "r"(a[2]), "r"(a[3]), "r"(b0), "r"(b1));
}

// ------------------------------ fp16 helpers -------------------------------
__device__ __forceinline__ void cvt4_half(__half* dst, float4 v) {
    __half2 h01 = __floats2half2_rn(v.x, v.y);
    __half2 h23 = __floats2half2_rn(v.z, v.w);
    *reinterpret_cast<__half2*>(dst)     = h01;
    *reinterpret_cast<__half2*>(dst + 2) = h23;
}

__device__ __forceinline__ void split4_half(__half* ph, __half* pl, float4 v) {
    __half2 h01 = __floats2half2_rn(v.x, v.y);
    __half2 h23 = __floats2half2_rn(v.z, v.w);
    float2 f01 = __half22float2(h01);
    float2 f23 = __half22float2(h23);
    __half2 l01 = __floats2half2_rn(v.x - f01.x, v.y - f01.y);
    __half2 l23 = __floats2half2_rn(v.z - f23.x, v.w - f23.y);
    *reinterpret_cast<__half2*>(ph)     = h01;
    *reinterpret_cast<__half2*>(ph + 2) = h23;
    *reinterpret_cast<__half2*>(pl)     = l01;
    *reinterpret_cast<__half2*>(pl + 2) = l23;
}

// ---------------------------------------------------------------------------
// HMMA GEMM: C[M,N] (+bias) = alpha * (Ah @ (Bh+Bl)^T)
//   Ah: fp16, M rows, K-major, ld = lda
//   Bh/Bl: fp16, N rows, K-major, ld = ldb
//   C: fp32 (OUT_HALF=0) or fp16 (OUT_HALF=1)
// CTA tile 256x128, BK=32, 3-stage cp.async ring (32 KB/stage, 96 KB).
// 8 warps: warp (wm = wid&3, wn = wid>>2) owns 64(m) x 64(n).
// Stage layout: A 16 KB | Bh 8 KB | Bl 8 KB, 64B rows, xor swizzle.
// ---------------------------------------------------------------------------
#define STAGE_BYTES 32768
#define GEMM_SMEM_BYTES (3 * STAGE_BYTES)

__device__ __forceinline__ uint32_t sw64(int row, int cb) {
    return (uint32_t)(row * 64 + (cb ^ (((row >> 1) & 3) << 4)));
}

__device__ __forceinline__ void load_stage(uint32_t sbase,
    const __half* Ah, const __half* Bh, const __half* Bl,
    int lda, int ldb, int k0, int tid)
{
    // A: 256 rows x 64B = 1024 16B chunks
#pragma unroll
    for (int i = 0; i < 4; i++) {
        const int idx = i * 256 + tid;          // 0..1023
        const int row = idx >> 2;               // 0..255
        const int cb  = (idx & 3) << 4;         // 0,16,32,48
        CP_ASYNC16(sbase + sw64(row, cb),
                   Ah + (long long)row * lda + k0 + (cb >> 1));
    }
    // Bh/Bl: 128 rows x 64B = 512 chunks each
#pragma unroll
    for (int i = 0; i < 2; i++) {
        const int idx = i * 256 + tid;          // 0..511
        const int row = idx >> 2;               // 0..127
        const int cb  = (idx & 3) << 4;
        const uint32_t soff = sw64(row, cb);
        const long long eb = (long long)row * ldb + k0 + (cb >> 1);
        CP_ASYNC16(sbase + 16384 + soff, Bh + eb);
        CP_ASYNC16(sbase + 24576 + soff, Bl + eb);
    }
}

template <bool HAS_BIAS, bool OUT_HALF>
__global__ void __launch_bounds__(256, 1)
tc_gemm_kernel(const __half* __restrict__ Ah,
               const __half* __restrict__ Bh, const __half* __restrict__ Bl,
               const float* __restrict__ bias, void* __restrict__ Cv,
               int K, int lda, int ldb, int ldc,
               long long sA, long long sB, long long sC, float alpha)
{
    extern __shared__ char smem[];
    const uint32_t sb = smem_u32(smem);
    const int tid  = threadIdx.x;
    const int lane = tid & 31;
    const int wid  = tid >> 5;
    const int wm = wid & 3;        // 4 warps along M (64 rows each)
    const int wn = wid >> 2;       // 2 warps along N (64 cols each)

    const int bx = blockIdx.x, by = blockIdx.y, bz = blockIdx.z;
    const long long aOff = (long long)bz * sA + (long long)by * 256 * lda;
    const long long bOff = (long long)bz * sB + (long long)bx * 128 * ldb;
    Ah += aOff; Bh += bOff; Bl += bOff;
    const long long cOff = (long long)bz * sC + (long long)by * 256 * ldc
                         + (long long)bx * 128;

    float acc[4][8][4];
#pragma unroll
    for (int i = 0; i < 4; i++)
#pragma unroll
        for (int j = 0; j < 8; j++)
#pragma unroll
            for (int q = 0; q < 4; q++) acc[i][j][q] = 0.0f;

    // hoisted fragment smem offsets (k16 = 0; k16 = 1 is XOR 32)
    const int cb0 = (lane >> 4) << 4;
    uint32_t offA[4], offB[4];
#pragma unroll
    for (int mt = 0; mt < 4; mt++)
        offA[mt] = sw64(wm * 64 + mt * 16 + (lane & 15), cb0);
#pragma unroll
    for (int ntp = 0; ntp < 4; ntp++)
        offB[ntp] = sw64(wn * 64 + ntp * 16 + (lane & 15), cb0);

    const int T = K >> 5;

    load_stage(sb,               Ah, Bh, Bl, lda, ldb,  0, tid);
    CP_ASYNC_COMMIT();
    load_stage(sb + STAGE_BYTES, Ah, Bh, Bl, lda, ldb, 32, tid);
    CP_ASYNC_COMMIT();

    for (int t = 0; t < T; t++) {
        if (t + 1 < T) { CP_ASYNC_WAIT(1); } else { CP_ASYNC_WAIT(0); }
        __syncthreads();            // stage t%3 ready for all; older stage free
        if (t + 2 < T) {
            load_stage(sb + ((t + 2) % 3) * STAGE_BYTES, Ah, Bh, Bl,
                       lda, ldb, (t + 2) << 5, tid);
            CP_ASYNC_COMMIT();
        }

        const uint32_t st = sb + (t % 3) * STAGE_BYTES;
#pragma unroll
        for (int k16 = 0; k16 < 2; k16++) {
            const uint32_t xk = (uint32_t)(k16 << 5);

            uint32_t a[4][4], b[4][4];
#pragma unroll
            for (int mt = 0; mt < 4; mt++) ldsm4(a[mt], st + (offA[mt] ^ xk));

            // term 1: Ah x Bh
#pragma unroll
            for (int ntp = 0; ntp < 4; ntp++)
                ldsm4(b[ntp], st + 16384 + (offB[ntp] ^ xk));
#pragma unroll
            for (int mt = 0; mt < 4; mt++)
#pragma unroll
                for (int ntp = 0; ntp < 4; ntp++)
#pragma unroll
                    for (int sub = 0; sub < 2; sub++)
                        mma_f16(acc[mt][ntp * 2 + sub], a[mt],
                                b[ntp][sub], b[ntp][sub + 2]);

            // term 2: Ah x Bl (overwrite b)
#pragma unroll
            for (int ntp = 0; ntp < 4; ntp++)
                ldsm4(b[ntp], st + 24576 + (offB[ntp] ^ xk));
#pragma unroll
            for (int mt = 0; mt < 4; mt++)
#pragma unroll
                for (int ntp = 0; ntp < 4; ntp++)
#pragma unroll
                    for (int sub = 0; sub < 2; sub++)
                        mma_f16(acc[mt][ntp * 2 + sub], a[mt],
                                b[ntp][sub], b[ntp][sub + 2]);
        }
    }

    // ---- epilogue ----
    const int rbase = wm * 64 + (lane >> 2);
    const int cbase = wn * 64 + (lane & 3) * 2;
#pragma unroll
    for (int mt = 0; mt < 4; mt++)
#pragma unroll
        for (int nt = 0; nt < 8; nt++) {
            const float* a = acc[mt][nt];
            const int m = rbase + mt * 16;
            const int n = cbase + nt * 8;
            float2 v0 = make_float2(a[0] * alpha, a[1] * alpha);
            float2 v1 = make_float2(a[2] * alpha, a[3] * alpha);
            if (HAS_BIAS) {
                const float b0 = bias[(long long)bx * 128 + n];
                const float b1 = bias[(long long)bx * 128 + n + 1];
                v0.x += b0; v0.y += b1; v1.x += b0; v1.y += b1;
            }
            if (OUT_HALF) {
                __half* C = (__half*)Cv + cOff;
                *reinterpret_cast<__half2*>(&C[(long long)m * ldc + n]) =
                    __floats2half2_rn(v0.x, v0.y);
                *reinterpret_cast<__half2*>(&C[(long long)(m + 8) * ldc + n]) =
                    __floats2half2_rn(v1.x, v1.y);
            } else {
                float* C = (float*)Cv + cOff;
                *reinterpret_cast<float2*>(&C[(long long)m * ldc + n]) = v0;
                *reinterpret_cast<float2*>(&C[(long long)(m + 8) * ldc + n]) = v1;
            }
        }
}

// ---------------------------------------------------------------------------
// elementwise fp32 -> single fp16
// ---------------------------------------------------------------------------
__global__ void __launch_bounds__(256)
cvt_half_kernel(const float* __restrict__ in, __half* __restrict__ oh, long long n)
{
    const long long i = ((long long)blockIdx.x * 256 + threadIdx.x) * 4;
    if (i >= n) return;
    cvt4_half(oh + i, *reinterpret_cast<const float4*>(&in[i]));
}

// ---------------------------------------------------------------------------
// transpose + split: out[c][r] = in[r][c]; out hi/lo fp16
// ---------------------------------------------------------------------------
__global__ void __launch_bounds__(256)
transpose_split_kernel(const float* __restrict__ in, int ld_in, long long strideIn,
                       __half* __restrict__ oh, __half* __restrict__ ol,
                       int ld_out, long long strideOut)
{
    __shared__ float t[32][33];
    const int bz = blockIdx.z;
    in += (long long)bz * strideIn;
    oh += (long long)bz * strideOut;
    ol += (long long)bz * strideOut;
    const int tx = threadIdx.x & 31, ty = threadIdx.x >> 5;
    const int r0 = blockIdx.y * 32, c0 = blockIdx.x * 32;
#pragma unroll
    for (int i = 0; i < 4; i++)
        t[ty + i * 8][tx] = in[(long long)(r0 + ty + i * 8) * ld_in + c0 + tx];
    __syncthreads();
#pragma unroll
    for (int i = 0; i < 4; i++) {
        const int oc = ty + i * 8;
        const float v = t[tx][oc];
        const __half h = __float2half_rn(v);
        const long long o = (long long)(c0 + oc) * ld_out + r0 + tx;
        oh[o] = h;
        ol[o] = __float2half_rn(v - __half2float(h));
    }
}

// ---------------------------------------------------------------------------
// split Q (single) and K (hi/lo) rows out of qkv fp32
// ---------------------------------------------------------------------------
__global__ void __launch_bounds__(256)
qk_split_kernel(const float* __restrict__ qkv,
                __half* __restrict__ Qh,
                __half* __restrict__ Kh, __half* __restrict__ Kl)
{
    const long long row = blockIdx.x;
    const float* src = qkv + row * 3 * DD;
    const int idx = threadIdx.x * 4;
    const float4 q  = *reinterpret_cast<const float4*>(&src[idx]);
    const float4 kk = *reinterpret_cast<const float4*>(&src[DD + idx]);
    cvt4_half(Qh + row * DD + idx, q);
    split4_half(Kh + row * DD + idx, Kl + row * DD + idx, kk);
}

// ---------------------------------------------------------------------------
// fused double-softmax with mask; outputs single fp16 probs
// ---------------------------------------------------------------------------
__device__ __forceinline__ float warpMax(float v) {
#pragma unroll
    for (int o = 16; o > 0; o >>= 1) v = fmaxf(v, __shfl_xor_sync(0xffffffffu, v, o));
    return v;
}
__device__ __forceinline__ float warpSum(float v) {
#pragma unroll
    for (int o = 16; o > 0; o >>= 1) v += __shfl_xor_sync(0xffffffffu, v, o);
    return v;
}
__device__ __forceinline__ float blockMax(float v, float* s) {
    const int w = threadIdx.x >> 5, l = threadIdx.x & 31;
    v = warpMax(v);
    __syncthreads();
    if (l == 0) s[w] = v;
    __syncthreads();
    float r = s[0];
#pragma unroll
    for (int i = 1; i < 8; i++) r = fmaxf(r, s[i]);
    return r;
}
__device__ __forceinline__ float blockSum(float v, float* s) {
    const int w = threadIdx.x >> 5, l = threadIdx.x & 31;
    v = warpSum(v);
    __syncthreads();
    if (l == 0) s[w] = v;
    __syncthreads();
    float r = s[0];
#pragma unroll
    for (int i = 1; i < 8; i++) r += s[i];
    return r;
}

__global__ __launch_bounds__(256)
void softmax_mask_kernel(const float* __restrict__ S, const int* __restrict__ mask,
                         __half* __restrict__ Ph)
{
    __shared__ float red[8];

    const long long row = (long long)blockIdx.y * NN + blockIdx.x;
    const float* srow = S + row * NN;
    const int* mrow = mask + row * NN;
    const int base = threadIdx.x * 8;

    float v[8];
    *reinterpret_cast<float4*>(&v[0]) = *reinterpret_cast<const float4*>(&srow[base]);
    *reinterpret_cast<float4*>(&v[4]) = *reinterpret_cast<const float4*>(&srow[base + 4]);

    float m = v[0];
#pragma unroll
    for (int i = 1; i < 8; i++) m = fmaxf(m, v[i]);
    m = blockMax(m, red);

    float p[8], lsum = 0.0f;
#pragma unroll
    for (int i = 0; i < 8; i++) { p[i] = __expf(v[i] - m); lsum += p[i]; }
    const float inv1 = 1.0f / blockSum(lsum, red);
#pragma unroll
    for (int i = 0; i < 8; i++) p[i] *= inv1;

    int mk[8];
    *reinterpret_cast<int4*>(&mk[0]) = *reinterpret_cast<const int4*>(&mrow[base]);
    *reinterpret_cast<int4*>(&mk[4]) = *reinterpret_cast<const int4*>(&mrow[base + 4]);

    float m2 = -3.0e38f;
#pragma unroll
    for (int i = 0; i < 8; i++) if (mk[i] != 0) m2 = fmaxf(m2, p[i]);
    m2 = blockMax(m2, red);

    float t[8], lsum2 = 0.0f;
#pragma unroll
    for (int i = 0; i < 8; i++) {
        t[i] = (mk[i] != 0) ? __expf(p[i] - m2) : 0.0f;
        lsum2 += t[i];
    }
    const float inv2 = 1.0f / blockSum(lsum2, red);

    float w[8];
#pragma unroll
    for (int i = 0; i < 8; i++) w[i] = t[i] * inv2;

    __half* ph = Ph + row * NN + base;
    cvt4_half(ph,     *reinterpret_cast<float4*>(&w[0]));
    cvt4_half(ph + 4, *reinterpret_cast<float4*>(&w[4]));
}

// ---------------------------------------------------------------------------
// Launch
// ---------------------------------------------------------------------------
extern "C" void kernel_launch(void* const* d_in, const int* in_sizes, int n_in,
                              void* d_out, int out_size)
{
    (void)in_sizes; (void)n_in; (void)out_size;

    const float* x    = (const float*)d_in[0];
    const int*   mask = (const int*)  d_in[1];
    const float* Wqkv = (const float*)d_in[2];
    const float* bqkv = (const float*)d_in[3];
    const float* Wout = (const float*)d_in[4];
    const float* bout = (const float*)d_in[5];
    float* out = (float*)d_out;

    cudaFuncSetAttribute(tc_gemm_kernel<true, false>,
                         cudaFuncAttributeMaxDynamicSharedMemorySize, GEMM_SMEM_BYTES);
    cudaFuncSetAttribute(tc_gemm_kernel<false, false>,
                         cudaFuncAttributeMaxDynamicSharedMemorySize, GEMM_SMEM_BYTES);
    cudaFuncSetAttribute(tc_gemm_kernel<false, true>,
                         cudaFuncAttributeMaxDynamicSharedMemorySize, GEMM_SMEM_BYTES);

    float *qkv, *scores;
    cudaGetSymbolAddress((void**)&qkv,    g_qkv);
    cudaGetSymbolAddress((void**)&scores, g_scores);
    __half *xh, *qh, *ph, *ath;
    __half *wqt_h, *wqt_l, *wot_h, *wot_l, *kh, *kl, *vth, *vtl;
    cudaGetSymbolAddress((void**)&xh, g_xh);
    cudaGetSymbolAddress((void**)&qh, g_qh);
    cudaGetSymbolAddress((void**)&ph, g_ph);
    cudaGetSymbolAddress((void**)&ath, g_ath);
    cudaGetSymbolAddress((void**)&wqt_h, g_wqt_h);
    cudaGetSymbolAddress((void**)&wqt_l, g_wqt_l);
    cudaGetSymbolAddress((void**)&wot_h, g_wot_h);
    cudaGetSymbolAddress((void**)&wot_l, g_wot_l);
    cudaGetSymbolAddress((void**)&kh, g_kh);
    cudaGetSymbolAddress((void**)&kl, g_kl);
    cudaGetSymbolAddress((void**)&vth, g_vth);
    cudaGetSymbolAddress((void**)&vtl, g_vtl);

    const long long nTok = (long long)BB * NN;           // 16384
    const long long sQ   = (long long)NN * DD;
    const long long sSC  = (long long)NN * NN;
    const long long sVT  = (long long)DD * NN;

    // 1) x -> fp16 (A side, single)
    cvt_half_kernel<<<(unsigned)(nTok * DD / 1024), 256>>>(x, xh, nTok * DD);

    // 2) transpose+split weights (B sides)
    transpose_split_kernel<<<dim3(3 * DD / 32, DD / 32, 1), 256>>>(
        Wqkv, 3 * DD, 0, wqt_h, wqt_l, DD, 0);
    transpose_split_kernel<<<dim3(DD / 32, DD / 32, 1), 256>>>(
        Wout, DD, 0, wot_h, wot_l, DD, 0);

    // 3) qkv = x @ W_qkv + b_qkv  (fp32 out)  M=16384 N=3072
    tc_gemm_kernel<true, false><<<dim3(3 * DD / 128, (unsigned)(nTok / 256), 1), 256,
                                  GEMM_SMEM_BYTES>>>(
        xh, wqt_h, wqt_l, bqkv, qkv, DD, DD, DD, 3 * DD, 0, 0, 0, 1.0f);

    // 4) Q (single) / K (split) ; V transposed (split)
    qk_split_kernel<<<(unsigned)nTok, 256>>>(qkv, qh, kh, kl);
    transpose_split_kernel<<<dim3(DD / 32, NN / 32, BB), 256>>>(
        qkv + 2 * DD, 3 * DD, (long long)NN * 3 * DD, vth, vtl, NN, sVT);

    // 5) scores = Q @ K^T / 32  (fp32 out)  M=2048 N=2048 per batch
    tc_gemm_kernel<false, false><<<dim3(NN / 128, NN / 256, BB), 256,
                                   GEMM_SMEM_BYTES>>>(
        qh, kh, kl, nullptr, scores, DD, DD, DD, NN, sQ, sQ, sSC, 0.03125f);

    // 6) double softmax + mask -> fp16 probs
    softmax_mask_kernel<<<dim3(NN, BB), 256>>>(scores, mask, ph);

    // 7) attn = P @ V  (fp16 out)  M=2048 N=1024 per batch
    tc_gemm_kernel<false, true><<<dim3(DD / 128, NN / 256, BB), 256,
                                  GEMM_SMEM_BYTES>>>(
        ph, vth, vtl, nullptr, ath, NN, NN, NN, DD, sSC, sVT, sQ, 1.0f);

    // 8) out = attn @ W_out + b_out  (fp32 out)  M=16384 N=1024
    tc_gemm_kernel<true, false><<<dim3(DD / 128, (unsigned)(nTok / 256), 1), 256,
                                  GEMM_SMEM_BYTES>>>(
        ath, wot_h, wot_l, bout, out, DD, DD, DD, DD, 0, 0, 0, 1.0f);
}